// round 10
// baseline (speedup 1.0000x reference)
#include <cuda_runtime.h>
#include <cuda_bf16.h>
#include <math.h>

#define FULLMASK 0xffffffffu

static const int N_ROI = 116;
static const int G     = 128;
static const int DEG   = 32;
static const int NN    = G * N_ROI;        // 14848 nodes
static const int EE    = G * N_ROI * DEG;  // 475136 edges
static const int EPG   = N_ROI * DEG;      // 3712 edges per graph
static const int HID   = 64;
static const int HC    = 256;
static const int MAXDEG = 192;

// ---------------- device scratch (allocation-free) ----------------
__device__ float  g_h0[NN * HID];
__device__ float  g_h1[NN * HID];
__device__ float  g_xl[NN * HC];
__device__ float  g_xr[NN * HC];
__device__ float  g_out[NN * HC];
__device__ int    g_nodelist[NN * MAXDEG];
__device__ int    g_srclist[NN * MAXDEG];
__device__ int    g_deg[NN];
__device__ float4 g_ea4[EE];              // edge_attr[0..3]
__device__ float  g_ea1[EE];              // edge_attr[4]
__device__ double g_csum0[HC];
__device__ double g_csq0[HC];
__device__ double g_csum1[HC];
__device__ double g_csq1[HC];

// ---------------- f32x2 packed-FMA helpers (Blackwell) ----------------
__device__ __forceinline__ unsigned long long pk2(float lo, float hi) {
    unsigned long long r;
    asm("mov.b64 %0, {%1, %2};" : "=l"(r) : "f"(lo), "f"(hi));
    return r;
}
__device__ __forceinline__ void ffma2(unsigned long long& d, unsigned long long a,
                                      unsigned long long b) {
    asm("fma.rn.f32x2 %0, %1, %2, %0;" : "+l"(d) : "l"(a), "l"(b));
}
__device__ __forceinline__ void unpk2(float& lo, float& hi, unsigned long long v) {
    asm("mov.b64 {%0, %1}, %2;" : "=f"(lo), "=f"(hi) : "l"(v));
}

// ---------------- edge_attr repack: [E][5] -> float4 + float -------------------
__global__ void prep_ea_k(const float* __restrict__ ea) {
    int e = blockIdx.x * 256 + threadIdx.x;
    if (e >= EE) return;
    const float* a = ea + (long)e * 5;
    g_ea4[e] = make_float4(a[0], a[1], a[2], a[3]);
    g_ea1[e] = a[4];
}

// ---------------- adjacency build: counting scatter, block per graph -----------
__global__ void build_adj_k(const int* __restrict__ srcA, const int* __restrict__ dst) {
    int g = blockIdx.x;
    int t = threadIdx.x;
    __shared__ int cnt[N_ROI];
    for (int i = t; i < N_ROI; i += 256) cnt[i] = 0;
    __syncthreads();
    int ebase = g * EPG, nbase = g * N_ROI;
    for (int e = t; e < EPG; e += 256) {
        int ge = ebase + e;
        int d = dst[ge] - nbase;
        int pos = atomicAdd(&cnt[d], 1);
        if (pos < MAXDEG) {
            int gn = nbase + d;
            g_nodelist[gn * MAXDEG + pos] = ge;
            g_srclist[gn * MAXDEG + pos] = srcA[ge];
        }
    }
    __syncthreads();
    for (int i = t; i < N_ROI; i += 256) g_deg[nbase + i] = min(cnt[i], MAXDEG);
}

// ---------------- node embed: 16-node tiles ----------------
__global__ void embed_k(const float* __restrict__ x, const int* __restrict__ node_group,
                        const float* __restrict__ gemb, const float* __restrict__ W,
                        const float* __restrict__ b) {
    int nb = blockIdx.x * 16;
    int t = threadIdx.x;   // 256
    __shared__ float sx[16][132];
    for (int i = t; i < 16 * 132; i += 256) {
        int j = i / 132, c = i - j * 132;
        sx[j][c] = (c < 116) ? x[(nb + j) * 116 + c]
                             : gemb[node_group[nb + j] * 16 + (c - 116)];
    }
    __syncthreads();
    int c = t & 63, jg = t >> 6;
    float bc = b[c];
    float a0 = bc, a1 = bc, a2 = bc, a3 = bc;
    #pragma unroll 4
    for (int r = 0; r < 132; r++) {
        float w = W[r * 64 + c];
        a0 += sx[jg][r] * w;
        a1 += sx[jg + 4][r] * w;
        a2 += sx[jg + 8][r] * w;
        a3 += sx[jg + 12][r] * w;
    }
    g_h0[(nb + jg) * 64 + c]      = a0 >= 0.f ? a0 : 0.01f * a0;
    g_h0[(nb + jg + 4) * 64 + c]  = a1 >= 0.f ? a1 : 0.01f * a1;
    g_h0[(nb + jg + 8) * 64 + c]  = a2 >= 0.f ? a2 : 0.01f * a2;
    g_h0[(nb + jg + 12) * 64 + c] = a3 >= 0.f ? a3 : 0.01f * a3;
}

// ---------------- GINE: 8 nodes/block, W1/W2 amortized ----------------
__global__ void __launch_bounds__(512) gine_k(
                       const float* __restrict__ We, const float* __restrict__ be,
                       const float* __restrict__ W1, const float* __restrict__ b1,
                       const float* __restrict__ W2, const float* __restrict__ b2,
                       const float* __restrict__ lng, const float* __restrict__ lnb) {
    int t = threadIdx.x;          // 512
    int j = t >> 6, c = t & 63;   // node-in-tile, channel
    int n = blockIdx.x * 8 + j;
    __shared__ float sh[8][64], sh2[8][64], ws[8][2], wq[8][2];
    float s = g_h0[n * 64 + c];
    int d = g_deg[n];
    const int* lst = g_nodelist + n * MAXDEG;
    const int* sl  = g_srclist  + n * MAXDEG;
    float bec = be[c];
    float w0 = We[c], w1 = We[64 + c], w2 = We[128 + c], w3 = We[192 + c], w4 = We[256 + c];
    int i0 = 0;
    for (; i0 + 4 <= d; i0 += 4) {
        int4 ev = *(const int4*)(lst + i0);
        int4 sv = *(const int4*)(sl + i0);
        float  hv0 = g_h0[sv.x * 64 + c], hv1 = g_h0[sv.y * 64 + c];
        float  hv2 = g_h0[sv.z * 64 + c], hv3 = g_h0[sv.w * 64 + c];
        float4 a0 = g_ea4[ev.x]; float a0e = g_ea1[ev.x];
        float4 a1 = g_ea4[ev.y]; float a1e = g_ea1[ev.y];
        float4 a2 = g_ea4[ev.z]; float a2e = g_ea1[ev.z];
        float4 a3 = g_ea4[ev.w]; float a3e = g_ea1[ev.w];
        float em0 = bec + a0.x * w0 + a0.y * w1 + a0.z * w2 + a0.w * w3 + a0e * w4;
        float em1 = bec + a1.x * w0 + a1.y * w1 + a1.z * w2 + a1.w * w3 + a1e * w4;
        float em2 = bec + a2.x * w0 + a2.y * w1 + a2.z * w2 + a2.w * w3 + a2e * w4;
        float em3 = bec + a3.x * w0 + a3.y * w1 + a3.z * w2 + a3.w * w3 + a3e * w4;
        em0 = em0 >= 0.f ? em0 : 0.01f * em0;
        em1 = em1 >= 0.f ? em1 : 0.01f * em1;
        em2 = em2 >= 0.f ? em2 : 0.01f * em2;
        em3 = em3 >= 0.f ? em3 : 0.01f * em3;
        float v0 = hv0 + em0, v1 = hv1 + em1, v2 = hv2 + em2, v3 = hv3 + em3;
        s += (v0 > 0.f ? v0 : 0.f) + (v1 > 0.f ? v1 : 0.f)
           + (v2 > 0.f ? v2 : 0.f) + (v3 > 0.f ? v3 : 0.f);
    }
    for (; i0 < d; i0++) {
        int e = lst[i0], src = sl[i0];
        float hv = g_h0[src * 64 + c];
        float4 a = g_ea4[e]; float ae = g_ea1[e];
        float em = bec + a.x * w0 + a.y * w1 + a.z * w2 + a.w * w3 + ae * w4;
        em = em >= 0.f ? em : 0.01f * em;
        float v = hv + em;
        s += v > 0.f ? v : 0.f;
    }
    sh[j][c] = s;
    __syncthreads();
    float acc = b1[c];
    #pragma unroll 8
    for (int r = 0; r < 64; r++) acc += sh[j][r] * W1[r * 64 + c];
    acc = acc >= 0.f ? acc : 0.01f * acc;
    sh2[j][c] = acc;
    __syncthreads();
    float acc2 = b2[c];
    #pragma unroll 8
    for (int r = 0; r < 64; r++) acc2 += sh2[j][r] * W2[r * 64 + c];
    acc2 = acc2 >= 0.f ? acc2 : 0.01f * acc2;
    float su = acc2, sq = acc2 * acc2;
    for (int o = 16; o; o >>= 1) {
        su += __shfl_down_sync(FULLMASK, su, o);
        sq += __shfl_down_sync(FULLMASK, sq, o);
    }
    int wn = (t >> 5) & 1;   // warp-within-node
    if ((t & 31) == 0) { ws[j][wn] = su; wq[j][wn] = sq; }
    __syncthreads();
    float mu  = (ws[j][0] + ws[j][1]) * (1.f / 64.f);
    float var = (wq[j][0] + wq[j][1]) * (1.f / 64.f) - mu * mu;
    g_h1[n * 64 + c] = (acc2 - mu) * rsqrtf(var + 1e-5f) * lng[c] + lnb[c];
}

// ---------------- xlxr layer 0: 32 nodes/block, scalar ----------------
__global__ void __launch_bounds__(512) xlxr0_k(const float* __restrict__ Wl,
                                               const float* __restrict__ Wr) {
    int nb = blockIdx.x * 32;
    int t = threadIdx.x;   // 512
    __shared__ float sh[32][HID];
    for (int i = t; i < 32 * 64; i += 512) {
        int j = i >> 6, c = i & 63;
        sh[j][c] = g_h1[(nb + j) * 64 + c];
    }
    __syncthreads();
    int ct = t & 255, half = (t >> 8) * 16;
    float al[16], ar[16];
    #pragma unroll
    for (int j = 0; j < 16; j++) { al[j] = 0.f; ar[j] = 0.f; }
    for (int r = 0; r < 64; r++) {
        float wl = Wl[r * 256 + ct], wr = Wr[r * 256 + ct];
        #pragma unroll
        for (int j = 0; j < 16; j++) {
            float hv = sh[half + j][r];
            al[j] += hv * wl;
            ar[j] += hv * wr;
        }
    }
    #pragma unroll
    for (int j = 0; j < 16; j++) {
        g_xl[(nb + half + j) * 256 + ct] = al[j];
        g_xr[(nb + half + j) * 256 + ct] = ar[j];
    }
}

// ---------------- xlxr layer 1: 32 nodes/block, f32x2, BN fused ----------------
__global__ void __launch_bounds__(512) xlxr1_k(const float* __restrict__ Wl,
                                               const float* __restrict__ Wr,
                                               const float* __restrict__ bng,
                                               const float* __restrict__ bnb) {
    int nb = blockIdx.x * 32;
    int t = threadIdx.x;   // 512
    __shared__ unsigned long long sh2[32][HC];   // h duplicated into both f32x2 lanes
    for (int i = t; i < 32 * 256; i += 512) {
        int j = i >> 8, c = i & 255;
        double mu_d  = g_csum0[c] * (1.0 / NN);
        double var_d = g_csq0[c] * (1.0 / NN) - mu_d * mu_d;
        float mu = (float)mu_d;
        float v = g_out[(nb + j) * 256 + c];
        v = (v - mu) * rsqrtf((float)var_d + 1e-5f) * bng[c] + bnb[c];
        v = v >= 0.f ? v : 0.01f * v;
        sh2[j][c] = pk2(v, v);
    }
    __syncthreads();
    int ct = t & 255, half = (t >> 8) * 16;
    unsigned long long acc[16];
    #pragma unroll
    for (int j = 0; j < 16; j++) acc[j] = 0ull;
    #pragma unroll 4
    for (int r = 0; r < 256; r++) {
        unsigned long long w2 = pk2(Wl[r * 256 + ct], Wr[r * 256 + ct]);
        #pragma unroll
        for (int j = 0; j < 16; j++) ffma2(acc[j], sh2[half + j][r], w2);
    }
    #pragma unroll
    for (int j = 0; j < 16; j++) {
        float lo, hi;
        unpk2(lo, hi, acc[j]);
        g_xl[(nb + half + j) * 256 + ct] = lo;
        g_xr[(nb + half + j) * 256 + ct] = hi;
    }
}

// ---------------- GATv2: 2 warps/node, 4 channels/lane, float4 gathers ----------
__global__ void __launch_bounds__(256) gat_warp_k(
    const float* __restrict__ WeP,   // [5,256]
    const float* __restrict__ attF,  // [4*64]
    double* __restrict__ csum, double* __restrict__ csq)
{
    __shared__ float bsum[HC], bsq[HC];
    int t = threadIdx.x, lane = t & 31, wid = t >> 5;
    for (int i = t; i < HC; i += 256) { bsum[i] = 0.f; bsq[i] = 0.f; }
    int n = blockIdx.x * 4 + (wid >> 1);
    int w = wid & 1;
    int c0 = w * 128 + lane * 4;
    float4 wp0 = *(const float4*)(WeP + c0);
    float4 wp1 = *(const float4*)(WeP + 256 + c0);
    float4 wp2 = *(const float4*)(WeP + 512 + c0);
    float4 wp3 = *(const float4*)(WeP + 768 + c0);
    float4 wp4 = *(const float4*)(WeP + 1024 + c0);
    float4 att = *(const float4*)(attF + c0);
    float4 xr  = *(const float4*)(g_xr + (long)n * 256 + c0);
    int d = g_deg[n];
    const int* lst = g_nodelist + n * MAXDEG;
    const int* sl  = g_srclist  + n * MAXDEG;
    float m = -1e30f, ssum = 0.f;
    float4 acc = make_float4(0.f, 0.f, 0.f, 0.f);
    __syncthreads();   // bsum/bsq init visible
    int i = 0;
    for (; i + 4 <= d; i += 4) {
        int4 ev = *(const int4*)(lst + i);
        int4 sv = *(const int4*)(sl + i);
        float4 x0 = *(const float4*)(g_xl + (long)sv.x * 256 + c0);
        float4 x1 = *(const float4*)(g_xl + (long)sv.y * 256 + c0);
        float4 x2 = *(const float4*)(g_xl + (long)sv.z * 256 + c0);
        float4 x3 = *(const float4*)(g_xl + (long)sv.w * 256 + c0);
        float4 a40 = g_ea4[ev.x]; float a10 = g_ea1[ev.x];
        float4 a41 = g_ea4[ev.y]; float a11 = g_ea1[ev.y];
        float4 a42 = g_ea4[ev.z]; float a12 = g_ea1[ev.z];
        float4 a43 = g_ea4[ev.w]; float a13 = g_ea1[ev.w];
        float p0, p1, p2, p3;
        {
            float zx = x0.x + xr.x + a40.x*wp0.x + a40.y*wp1.x + a40.z*wp2.x + a40.w*wp3.x + a10*wp4.x;
            float zy = x0.y + xr.y + a40.x*wp0.y + a40.y*wp1.y + a40.z*wp2.y + a40.w*wp3.y + a10*wp4.y;
            float zz = x0.z + xr.z + a40.x*wp0.z + a40.y*wp1.z + a40.z*wp2.z + a40.w*wp3.z + a10*wp4.z;
            float zw = x0.w + xr.w + a40.x*wp0.w + a40.y*wp1.w + a40.z*wp2.w + a40.w*wp3.w + a10*wp4.w;
            zx = zx >= 0.f ? zx : 0.2f * zx; zy = zy >= 0.f ? zy : 0.2f * zy;
            zz = zz >= 0.f ? zz : 0.2f * zz; zw = zw >= 0.f ? zw : 0.2f * zw;
            p0 = zx*att.x + zy*att.y + zz*att.z + zw*att.w;
        }
        {
            float zx = x1.x + xr.x + a41.x*wp0.x + a41.y*wp1.x + a41.z*wp2.x + a41.w*wp3.x + a11*wp4.x;
            float zy = x1.y + xr.y + a41.x*wp0.y + a41.y*wp1.y + a41.z*wp2.y + a41.w*wp3.y + a11*wp4.y;
            float zz = x1.z + xr.z + a41.x*wp0.z + a41.y*wp1.z + a41.z*wp2.z + a41.w*wp3.z + a11*wp4.z;
            float zw = x1.w + xr.w + a41.x*wp0.w + a41.y*wp1.w + a41.z*wp2.w + a41.w*wp3.w + a11*wp4.w;
            zx = zx >= 0.f ? zx : 0.2f * zx; zy = zy >= 0.f ? zy : 0.2f * zy;
            zz = zz >= 0.f ? zz : 0.2f * zz; zw = zw >= 0.f ? zw : 0.2f * zw;
            p1 = zx*att.x + zy*att.y + zz*att.z + zw*att.w;
        }
        {
            float zx = x2.x + xr.x + a42.x*wp0.x + a42.y*wp1.x + a42.z*wp2.x + a42.w*wp3.x + a12*wp4.x;
            float zy = x2.y + xr.y + a42.x*wp0.y + a42.y*wp1.y + a42.z*wp2.y + a42.w*wp3.y + a12*wp4.y;
            float zz = x2.z + xr.z + a42.x*wp0.z + a42.y*wp1.z + a42.z*wp2.z + a42.w*wp3.z + a12*wp4.z;
            float zw = x2.w + xr.w + a42.x*wp0.w + a42.y*wp1.w + a42.z*wp2.w + a42.w*wp3.w + a12*wp4.w;
            zx = zx >= 0.f ? zx : 0.2f * zx; zy = zy >= 0.f ? zy : 0.2f * zy;
            zz = zz >= 0.f ? zz : 0.2f * zz; zw = zw >= 0.f ? zw : 0.2f * zw;
            p2 = zx*att.x + zy*att.y + zz*att.z + zw*att.w;
        }
        {
            float zx = x3.x + xr.x + a43.x*wp0.x + a43.y*wp1.x + a43.z*wp2.x + a43.w*wp3.x + a13*wp4.x;
            float zy = x3.y + xr.y + a43.x*wp0.y + a43.y*wp1.y + a43.z*wp2.y + a43.w*wp3.y + a13*wp4.y;
            float zz = x3.z + xr.z + a43.x*wp0.z + a43.y*wp1.z + a43.z*wp2.z + a43.w*wp3.z + a13*wp4.z;
            float zw = x3.w + xr.w + a43.x*wp0.w + a43.y*wp1.w + a43.z*wp2.w + a43.w*wp3.w + a13*wp4.w;
            zx = zx >= 0.f ? zx : 0.2f * zx; zy = zy >= 0.f ? zy : 0.2f * zy;
            zz = zz >= 0.f ? zz : 0.2f * zz; zw = zw >= 0.f ? zw : 0.2f * zw;
            p3 = zx*att.x + zy*att.y + zz*att.z + zw*att.w;
        }
        #pragma unroll
        for (int o = 8; o; o >>= 1) {   // reduce within 16-lane half-warp (one head)
            p0 += __shfl_xor_sync(FULLMASK, p0, o);
            p1 += __shfl_xor_sync(FULLMASK, p1, o);
            p2 += __shfl_xor_sync(FULLMASK, p2, o);
            p3 += __shfl_xor_sync(FULLMASK, p3, o);
        }
        float mx = fmaxf(fmaxf(fmaxf(p0, p1), fmaxf(p2, p3)), m);
        float f  = __expf(m - mx);
        float w0 = __expf(p0 - mx), w1 = __expf(p1 - mx),
              w2 = __expf(p2 - mx), w3 = __expf(p3 - mx);
        ssum = ssum * f + ((w0 + w1) + (w2 + w3));
        acc.x = acc.x * f + ((w0*x0.x + w1*x1.x) + (w2*x2.x + w3*x3.x));
        acc.y = acc.y * f + ((w0*x0.y + w1*x1.y) + (w2*x2.y + w3*x3.y));
        acc.z = acc.z * f + ((w0*x0.z + w1*x1.z) + (w2*x2.z + w3*x3.z));
        acc.w = acc.w * f + ((w0*x0.w + w1*x1.w) + (w2*x2.w + w3*x3.w));
        m = mx;
    }
    for (; i < d; i++) {
        int e = lst[i], s0 = sl[i];
        float4 x0 = *(const float4*)(g_xl + (long)s0 * 256 + c0);
        float4 a4 = g_ea4[e]; float a1e = g_ea1[e];
        float zx = x0.x + xr.x + a4.x*wp0.x + a4.y*wp1.x + a4.z*wp2.x + a4.w*wp3.x + a1e*wp4.x;
        float zy = x0.y + xr.y + a4.x*wp0.y + a4.y*wp1.y + a4.z*wp2.y + a4.w*wp3.y + a1e*wp4.y;
        float zz = x0.z + xr.z + a4.x*wp0.z + a4.y*wp1.z + a4.z*wp2.z + a4.w*wp3.z + a1e*wp4.z;
        float zw = x0.w + xr.w + a4.x*wp0.w + a4.y*wp1.w + a4.z*wp2.w + a4.w*wp3.w + a1e*wp4.w;
        zx = zx >= 0.f ? zx : 0.2f * zx; zy = zy >= 0.f ? zy : 0.2f * zy;
        zz = zz >= 0.f ? zz : 0.2f * zz; zw = zw >= 0.f ? zw : 0.2f * zw;
        float p0 = zx*att.x + zy*att.y + zz*att.z + zw*att.w;
        #pragma unroll
        for (int o = 8; o; o >>= 1) p0 += __shfl_xor_sync(FULLMASK, p0, o);
        float mx = fmaxf(m, p0);
        float f = __expf(m - mx), w0 = __expf(p0 - mx);
        ssum = ssum * f + w0;
        acc.x = acc.x * f + w0 * x0.x;
        acc.y = acc.y * f + w0 * x0.y;
        acc.z = acc.z * f + w0 * x0.z;
        acc.w = acc.w * f + w0 * x0.w;
        m = mx;
    }
    float inv = 1.f / (ssum + 1e-16f);
    float4 o4 = make_float4(acc.x * inv, acc.y * inv, acc.z * inv, acc.w * inv);
    *(float4*)(g_out + (long)n * 256 + c0) = o4;
    atomicAdd(&bsum[c0],     o4.x); atomicAdd(&bsq[c0],     o4.x * o4.x);
    atomicAdd(&bsum[c0 + 1], o4.y); atomicAdd(&bsq[c0 + 1], o4.y * o4.y);
    atomicAdd(&bsum[c0 + 2], o4.z); atomicAdd(&bsq[c0 + 2], o4.z * o4.z);
    atomicAdd(&bsum[c0 + 3], o4.w); atomicAdd(&bsq[c0 + 3], o4.w * o4.w);
    __syncthreads();
    if (t < HC) {
        atomicAdd(&csum[t], (double)bsum[t]);
        atomicAdd(&csq[t],  (double)bsq[t]);
    }
}

// ---------------- zero BN stat buffers (double) ----------------
__global__ void zero_stats_k() {
    int t = threadIdx.x;
    g_csum0[t] = 0.0; g_csq0[t] = 0.0;
    g_csum1[t] = 0.0; g_csq1[t] = 0.0;
}

// ---------------- pool + classifier (BN+leaky of layer 1 fused in) -------------
__global__ void pool_k(const float* __restrict__ W, const float* __restrict__ bb,
                       const float* __restrict__ gam, const float* __restrict__ bet,
                       float* __restrict__ outp) {
    int g = blockIdx.x;
    int t = threadIdx.x;  // 256 = channel
    double mu_d  = g_csum1[t] * (1.0 / NN);
    double var_d = g_csq1[t] * (1.0 / NN) - mu_d * mu_d;
    float mu = (float)mu_d;
    float rs = rsqrtf((float)var_d + 1e-5f) * gam[t];
    float bt = bet[t];
    float s = 0.f;
    int base = g * N_ROI;
    for (int r = 0; r < N_ROI; r++) {
        float v = g_out[(base + r) * 256 + t];
        v = (v - mu) * rs + bt;
        v = v >= 0.f ? v : 0.01f * v;
        s += v;
    }
    s *= (1.f / (float)N_ROI);
    float c0 = s * W[t * 2], c1 = s * W[t * 2 + 1];
    __shared__ float r0s[8], r1s[8];
    for (int o = 16; o; o >>= 1) {
        c0 += __shfl_down_sync(FULLMASK, c0, o);
        c1 += __shfl_down_sync(FULLMASK, c1, o);
    }
    if ((t & 31) == 0) { r0s[t >> 5] = c0; r1s[t >> 5] = c1; }
    __syncthreads();
    if (t == 0) {
        float a = 0.f, b2 = 0.f;
        for (int i = 0; i < 8; i++) { a += r0s[i]; b2 += r1s[i]; }
        outp[g * 2]     = a  + bb[0];
        outp[g * 2 + 1] = b2 + bb[1];
    }
}

// ---------------- launch --------------------------------------------------------
extern "C" void kernel_launch(void* const* d_in, const int* in_sizes, int n_in,
                              void* d_out, int out_size) {
    const float* x          = (const float*)d_in[0];
    const int*   edge_index = (const int*)  d_in[1];
    const float* edge_attr  = (const float*)d_in[2];
    const int*   node_group = (const int*)  d_in[4];
    const float* group_emb  = (const float*)d_in[5];
    const float* W_embed    = (const float*)d_in[6];
    const float* b_embed    = (const float*)d_in[7];
    const float* We_enc     = (const float*)d_in[8];
    const float* be_enc     = (const float*)d_in[9];
    const float* W1         = (const float*)d_in[10];
    const float* b1         = (const float*)d_in[11];
    const float* W2         = (const float*)d_in[12];
    const float* b2         = (const float*)d_in[13];
    const float* ln_g       = (const float*)d_in[14];
    const float* ln_b       = (const float*)d_in[15];
    const float* l0_Wl      = (const float*)d_in[16];
    const float* l0_Wr      = (const float*)d_in[17];
    const float* l0_We      = (const float*)d_in[18];
    const float* l0_att     = (const float*)d_in[19];
    const float* l0_bn_g    = (const float*)d_in[21];
    const float* l0_bn_b    = (const float*)d_in[22];
    const float* l1_Wl      = (const float*)d_in[23];
    const float* l1_Wr      = (const float*)d_in[24];
    const float* l1_We      = (const float*)d_in[25];
    const float* l1_att     = (const float*)d_in[26];
    const float* l1_bn_g    = (const float*)d_in[28];
    const float* l1_bn_b    = (const float*)d_in[29];
    const float* fc2_W      = (const float*)d_in[30];
    const float* fc2_b      = (const float*)d_in[31];

    const int* srcp = edge_index;
    const int* dstp = edge_index + EE;

    double* csum0; double* csq0; double* csum1; double* csq1;
    cudaGetSymbolAddress((void**)&csum0, g_csum0);
    cudaGetSymbolAddress((void**)&csq0,  g_csq0);
    cudaGetSymbolAddress((void**)&csum1, g_csum1);
    cudaGetSymbolAddress((void**)&csq1,  g_csq1);

    // launch order chosen so the profiled slot (#4) lands on the new gine_k
    embed_k<<<NN / 16, 256>>>(x, node_group, group_emb, W_embed, b_embed);   // 1
    prep_ea_k<<<(EE + 255) / 256, 256>>>(edge_attr);                          // 2
    build_adj_k<<<G, 256>>>(srcp, dstp);                                      // 3
    gine_k<<<NN / 8, 512>>>(We_enc, be_enc, W1, b1, W2, b2, ln_g, ln_b);      // 4 (profiled)
    zero_stats_k<<<1, 256>>>();                                               // 5

    // GAT layer 0 (BN stats fused, double atomics)
    xlxr0_k<<<NN / 32, 512>>>(l0_Wl, l0_Wr);
    gat_warp_k<<<NN / 4, 256>>>(l0_We, l0_att, csum0, csq0);

    // GAT layer 1 (BN of layer 0 fused into xlxr1 input load)
    xlxr1_k<<<NN / 32, 512>>>(l1_Wl, l1_Wr, l0_bn_g, l0_bn_b);
    gat_warp_k<<<NN / 4, 256>>>(l1_We, l1_att, csum1, csq1);

    // pool + classifier (BN of layer 1 fused in)
    pool_k<<<G, 256>>>(fc2_W, fc2_b, l1_bn_g, l1_bn_b, (float*)d_out);
}

// round 11
// speedup vs baseline: 1.1519x; 1.1519x over previous
#include <cuda_runtime.h>
#include <cuda_bf16.h>
#include <math.h>

#define FULLMASK 0xffffffffu

static const int N_ROI = 116;
static const int G     = 128;
static const int DEG   = 32;
static const int NN    = G * N_ROI;        // 14848 nodes
static const int EE    = G * N_ROI * DEG;  // 475136 edges
static const int EPG   = N_ROI * DEG;      // 3712 edges per graph
static const int HID   = 64;
static const int HC    = 256;
static const int MAXDEG = 192;

// grid partition for the fused prologue
static const int PB_EMBED = NN / 16;            // 928
static const int PB_ADJ   = PB_EMBED + G;       // 1056
static const int PB_EA    = PB_ADJ + EE / 256;  // 1056 + 1856 = 2912
static const int PB_TOTAL = PB_EA + 1;          // 2913 (last block zeroes stats)

// ---------------- device scratch (allocation-free) ----------------
__device__ float  g_h0[NN * HID];
__device__ float  g_h1[NN * HID];
__device__ float  g_xl[NN * HC];
__device__ float  g_xr[NN * HC];
__device__ float  g_out[NN * HC];
__device__ int    g_nodelist[NN * MAXDEG];
__device__ int    g_srclist[NN * MAXDEG];
__device__ int    g_deg[NN];
__device__ float4 g_ea4[EE];              // edge_attr[0..3]
__device__ float  g_ea1[EE];              // edge_attr[4]
__device__ double g_csum0[HC];
__device__ double g_csq0[HC];
__device__ double g_csum1[HC];
__device__ double g_csq1[HC];

// ---------------- f32x2 packed-FMA helpers (Blackwell) ----------------
__device__ __forceinline__ unsigned long long pk2(float lo, float hi) {
    unsigned long long r;
    asm("mov.b64 %0, {%1, %2};" : "=l"(r) : "f"(lo), "f"(hi));
    return r;
}
__device__ __forceinline__ void ffma2(unsigned long long& d, unsigned long long a,
                                      unsigned long long b) {
    asm("fma.rn.f32x2 %0, %1, %2, %0;" : "+l"(d) : "l"(a), "l"(b));
}
__device__ __forceinline__ void unpk2(float& lo, float& hi, unsigned long long v) {
    asm("mov.b64 {%0, %1}, %2;" : "=f"(lo), "=f"(hi) : "l"(v));
}

// ---------------- fused prologue: embed | build_adj | ea repack | zero stats ----
__global__ void prologue_k(const float* __restrict__ x, const int* __restrict__ node_group,
                           const float* __restrict__ gemb, const float* __restrict__ W,
                           const float* __restrict__ b,
                           const int* __restrict__ srcA, const int* __restrict__ dst,
                           const float* __restrict__ ea) {
    int bid = blockIdx.x;
    int t = threadIdx.x;   // 256
    if (bid < PB_EMBED) {
        // ---- node embed, 16-node tile ----
        __shared__ float sx[16][132];
        int nb = bid * 16;
        for (int i = t; i < 16 * 132; i += 256) {
            int j = i / 132, c = i - j * 132;
            sx[j][c] = (c < 116) ? x[(nb + j) * 116 + c]
                                 : gemb[node_group[nb + j] * 16 + (c - 116)];
        }
        __syncthreads();
        int c = t & 63, jg = t >> 6;
        float bc = b[c];
        float a0 = bc, a1 = bc, a2 = bc, a3 = bc;
        #pragma unroll 4
        for (int r = 0; r < 132; r++) {
            float w = W[r * 64 + c];
            a0 += sx[jg][r] * w;
            a1 += sx[jg + 4][r] * w;
            a2 += sx[jg + 8][r] * w;
            a3 += sx[jg + 12][r] * w;
        }
        g_h0[(nb + jg) * 64 + c]      = a0 >= 0.f ? a0 : 0.01f * a0;
        g_h0[(nb + jg + 4) * 64 + c]  = a1 >= 0.f ? a1 : 0.01f * a1;
        g_h0[(nb + jg + 8) * 64 + c]  = a2 >= 0.f ? a2 : 0.01f * a2;
        g_h0[(nb + jg + 12) * 64 + c] = a3 >= 0.f ? a3 : 0.01f * a3;
    } else if (bid < PB_ADJ) {
        // ---- adjacency build (counting scatter) for graph g ----
        __shared__ int cnt[N_ROI];
        int g = bid - PB_EMBED;
        for (int i = t; i < N_ROI; i += 256) cnt[i] = 0;
        __syncthreads();
        int ebase = g * EPG, nbase = g * N_ROI;
        for (int e = t; e < EPG; e += 256) {
            int ge = ebase + e;
            int d = dst[ge] - nbase;
            int pos = atomicAdd(&cnt[d], 1);
            if (pos < MAXDEG) {
                int gn = nbase + d;
                g_nodelist[gn * MAXDEG + pos] = ge;
                g_srclist[gn * MAXDEG + pos] = srcA[ge];
            }
        }
        __syncthreads();
        for (int i = t; i < N_ROI; i += 256) g_deg[nbase + i] = min(cnt[i], MAXDEG);
    } else if (bid < PB_EA) {
        // ---- edge_attr repack ----
        int e = (bid - PB_ADJ) * 256 + t;
        if (e < EE) {
            const float* a = ea + (long)e * 5;
            g_ea4[e] = make_float4(a[0], a[1], a[2], a[3]);
            g_ea1[e] = a[4];
        }
    } else {
        // ---- zero BN stat buffers ----
        g_csum0[t] = 0.0; g_csq0[t] = 0.0;
        g_csum1[t] = 0.0; g_csq1[t] = 0.0;
    }
}

// ---------------- GINE aggregate + MLP + LayerNorm (R9 shape: 64 thr/node) -----
__global__ void gine_k(const float* __restrict__ We, const float* __restrict__ be,
                       const float* __restrict__ W1, const float* __restrict__ b1,
                       const float* __restrict__ W2, const float* __restrict__ b2,
                       const float* __restrict__ lng, const float* __restrict__ lnb) {
    int n = blockIdx.x;
    int t = threadIdx.x;   // 64
    __shared__ float sh[64], sh2[64], ws[2], wq[2];
    float s = g_h0[n * 64 + t];
    int d = g_deg[n];
    const int* lst = g_nodelist + n * MAXDEG;
    const int* sl  = g_srclist  + n * MAXDEG;
    float bec = be[t];
    float w0 = We[t], w1 = We[64 + t], w2 = We[128 + t], w3 = We[192 + t], w4 = We[256 + t];
    int i0 = 0;
    for (; i0 + 4 <= d; i0 += 4) {
        int4 ev = *(const int4*)(lst + i0);
        int4 sv = *(const int4*)(sl + i0);
        float  hv0 = g_h0[sv.x * 64 + t], hv1 = g_h0[sv.y * 64 + t];
        float  hv2 = g_h0[sv.z * 64 + t], hv3 = g_h0[sv.w * 64 + t];
        float4 a0 = g_ea4[ev.x]; float a0e = g_ea1[ev.x];
        float4 a1 = g_ea4[ev.y]; float a1e = g_ea1[ev.y];
        float4 a2 = g_ea4[ev.z]; float a2e = g_ea1[ev.z];
        float4 a3 = g_ea4[ev.w]; float a3e = g_ea1[ev.w];
        float em0 = bec + a0.x * w0 + a0.y * w1 + a0.z * w2 + a0.w * w3 + a0e * w4;
        float em1 = bec + a1.x * w0 + a1.y * w1 + a1.z * w2 + a1.w * w3 + a1e * w4;
        float em2 = bec + a2.x * w0 + a2.y * w1 + a2.z * w2 + a2.w * w3 + a2e * w4;
        float em3 = bec + a3.x * w0 + a3.y * w1 + a3.z * w2 + a3.w * w3 + a3e * w4;
        em0 = em0 >= 0.f ? em0 : 0.01f * em0;
        em1 = em1 >= 0.f ? em1 : 0.01f * em1;
        em2 = em2 >= 0.f ? em2 : 0.01f * em2;
        em3 = em3 >= 0.f ? em3 : 0.01f * em3;
        float v0 = hv0 + em0, v1 = hv1 + em1, v2 = hv2 + em2, v3 = hv3 + em3;
        s += (v0 > 0.f ? v0 : 0.f) + (v1 > 0.f ? v1 : 0.f)
           + (v2 > 0.f ? v2 : 0.f) + (v3 > 0.f ? v3 : 0.f);
    }
    for (; i0 < d; i0++) {
        int e = lst[i0], src = sl[i0];
        float hv = g_h0[src * 64 + t];
        float4 a = g_ea4[e]; float ae = g_ea1[e];
        float em = bec + a.x * w0 + a.y * w1 + a.z * w2 + a.w * w3 + ae * w4;
        em = em >= 0.f ? em : 0.01f * em;
        float v = hv + em;
        s += v > 0.f ? v : 0.f;
    }
    sh[t] = s;
    __syncthreads();
    float acc = b1[t];
    #pragma unroll 8
    for (int r = 0; r < 64; r++) acc += sh[r] * W1[r * 64 + t];
    acc = acc >= 0.f ? acc : 0.01f * acc;
    sh2[t] = acc;
    __syncthreads();
    float acc2 = b2[t];
    #pragma unroll 8
    for (int r = 0; r < 64; r++) acc2 += sh2[r] * W2[r * 64 + t];
    acc2 = acc2 >= 0.f ? acc2 : 0.01f * acc2;
    float su = acc2, sq = acc2 * acc2;
    for (int o = 16; o; o >>= 1) {
        su += __shfl_down_sync(FULLMASK, su, o);
        sq += __shfl_down_sync(FULLMASK, sq, o);
    }
    if ((t & 31) == 0) { ws[t >> 5] = su; wq[t >> 5] = sq; }
    __syncthreads();
    float mu  = (ws[0] + ws[1]) * (1.f / 64.f);
    float var = (wq[0] + wq[1]) * (1.f / 64.f) - mu * mu;
    g_h1[n * 64 + t] = (acc2 - mu) * rsqrtf(var + 1e-5f) * lng[t] + lnb[t];
}

// ---------------- xlxr layer 0: 16 nodes/block, scalar (R9 shape) --------------
__global__ void xlxr0_k(const float* __restrict__ Wl, const float* __restrict__ Wr) {
    int nb = blockIdx.x * 16;
    int t = threadIdx.x;   // 256
    __shared__ float sh[16][HID];
    for (int i = t; i < 16 * 64; i += 256) {
        int j = i >> 6, c = i & 63;
        sh[j][c] = g_h1[(nb + j) * 64 + c];
    }
    __syncthreads();
    float al[16], ar[16];
    #pragma unroll
    for (int j = 0; j < 16; j++) { al[j] = 0.f; ar[j] = 0.f; }
    for (int r = 0; r < 64; r++) {
        float wl = Wl[r * 256 + t], wr = Wr[r * 256 + t];
        #pragma unroll
        for (int j = 0; j < 16; j++) {
            float hv = sh[j][r];
            al[j] += hv * wl;
            ar[j] += hv * wr;
        }
    }
    #pragma unroll
    for (int j = 0; j < 16; j++) {
        g_xl[(nb + j) * 256 + t] = al[j];
        g_xr[(nb + j) * 256 + t] = ar[j];
    }
}

// ---------------- xlxr layer 1: 16 nodes/block, f32x2, BN fused (R9 shape) ------
__global__ void xlxr1_k(const float* __restrict__ Wl, const float* __restrict__ Wr,
                        const float* __restrict__ bng, const float* __restrict__ bnb) {
    int nb = blockIdx.x * 16;
    int t = threadIdx.x;   // 256
    __shared__ unsigned long long sh2[16][HC];
    for (int i = t; i < 16 * 256; i += 256) {
        int j = i >> 8, c = i & 255;
        double mu_d  = g_csum0[c] * (1.0 / NN);
        double var_d = g_csq0[c] * (1.0 / NN) - mu_d * mu_d;
        float mu = (float)mu_d;
        float v = g_out[(nb + j) * 256 + c];
        v = (v - mu) * rsqrtf((float)var_d + 1e-5f) * bng[c] + bnb[c];
        v = v >= 0.f ? v : 0.01f * v;
        sh2[j][c] = pk2(v, v);
    }
    __syncthreads();
    unsigned long long acc[16];
    #pragma unroll
    for (int j = 0; j < 16; j++) acc[j] = 0ull;
    #pragma unroll 4
    for (int r = 0; r < 256; r++) {
        unsigned long long w2 = pk2(Wl[r * 256 + t], Wr[r * 256 + t]);
        #pragma unroll
        for (int j = 0; j < 16; j++) ffma2(acc[j], sh2[j][r], w2);
    }
    #pragma unroll
    for (int j = 0; j < 16; j++) {
        float lo, hi;
        unpk2(lo, hi, acc[j]);
        g_xl[(nb + j) * 256 + t] = lo;
        g_xr[(nb + j) * 256 + t] = hi;
    }
}

// ---------------- GATv2: 2 warps/node, 4 channels/lane, float4 gathers ----------
__global__ void __launch_bounds__(256) gat_warp_k(
    const float* __restrict__ WeP,   // [5,256]
    const float* __restrict__ attF,  // [4*64]
    double* __restrict__ csum, double* __restrict__ csq)
{
    __shared__ float bsum[HC], bsq[HC];
    int t = threadIdx.x, lane = t & 31, wid = t >> 5;
    for (int i = t; i < HC; i += 256) { bsum[i] = 0.f; bsq[i] = 0.f; }
    int n = blockIdx.x * 4 + (wid >> 1);
    int w = wid & 1;
    int c0 = w * 128 + lane * 4;
    float4 wp0 = *(const float4*)(WeP + c0);
    float4 wp1 = *(const float4*)(WeP + 256 + c0);
    float4 wp2 = *(const float4*)(WeP + 512 + c0);
    float4 wp3 = *(const float4*)(WeP + 768 + c0);
    float4 wp4 = *(const float4*)(WeP + 1024 + c0);
    float4 att = *(const float4*)(attF + c0);
    float4 xr  = *(const float4*)(g_xr + (long)n * 256 + c0);
    int d = g_deg[n];
    const int* lst = g_nodelist + n * MAXDEG;
    const int* sl  = g_srclist  + n * MAXDEG;
    float m = -1e30f, ssum = 0.f;
    float4 acc = make_float4(0.f, 0.f, 0.f, 0.f);
    __syncthreads();   // bsum/bsq init visible
    int i = 0;
    for (; i + 4 <= d; i += 4) {
        int4 ev = *(const int4*)(lst + i);
        int4 sv = *(const int4*)(sl + i);
        float4 x0 = *(const float4*)(g_xl + (long)sv.x * 256 + c0);
        float4 x1 = *(const float4*)(g_xl + (long)sv.y * 256 + c0);
        float4 x2 = *(const float4*)(g_xl + (long)sv.z * 256 + c0);
        float4 x3 = *(const float4*)(g_xl + (long)sv.w * 256 + c0);
        float4 a40 = g_ea4[ev.x]; float a10 = g_ea1[ev.x];
        float4 a41 = g_ea4[ev.y]; float a11 = g_ea1[ev.y];
        float4 a42 = g_ea4[ev.z]; float a12 = g_ea1[ev.z];
        float4 a43 = g_ea4[ev.w]; float a13 = g_ea1[ev.w];
        float p0, p1, p2, p3;
        {
            float zx = x0.x + xr.x + a40.x*wp0.x + a40.y*wp1.x + a40.z*wp2.x + a40.w*wp3.x + a10*wp4.x;
            float zy = x0.y + xr.y + a40.x*wp0.y + a40.y*wp1.y + a40.z*wp2.y + a40.w*wp3.y + a10*wp4.y;
            float zz = x0.z + xr.z + a40.x*wp0.z + a40.y*wp1.z + a40.z*wp2.z + a40.w*wp3.z + a10*wp4.z;
            float zw = x0.w + xr.w + a40.x*wp0.w + a40.y*wp1.w + a40.z*wp2.w + a40.w*wp3.w + a10*wp4.w;
            zx = zx >= 0.f ? zx : 0.2f * zx; zy = zy >= 0.f ? zy : 0.2f * zy;
            zz = zz >= 0.f ? zz : 0.2f * zz; zw = zw >= 0.f ? zw : 0.2f * zw;
            p0 = zx*att.x + zy*att.y + zz*att.z + zw*att.w;
        }
        {
            float zx = x1.x + xr.x + a41.x*wp0.x + a41.y*wp1.x + a41.z*wp2.x + a41.w*wp3.x + a11*wp4.x;
            float zy = x1.y + xr.y + a41.x*wp0.y + a41.y*wp1.y + a41.z*wp2.y + a41.w*wp3.y + a11*wp4.y;
            float zz = x1.z + xr.z + a41.x*wp0.z + a41.y*wp1.z + a41.z*wp2.z + a41.w*wp3.z + a11*wp4.z;
            float zw = x1.w + xr.w + a41.x*wp0.w + a41.y*wp1.w + a41.z*wp2.w + a41.w*wp3.w + a11*wp4.w;
            zx = zx >= 0.f ? zx : 0.2f * zx; zy = zy >= 0.f ? zy : 0.2f * zy;
            zz = zz >= 0.f ? zz : 0.2f * zz; zw = zw >= 0.f ? zw : 0.2f * zw;
            p1 = zx*att.x + zy*att.y + zz*att.z + zw*att.w;
        }
        {
            float zx = x2.x + xr.x + a42.x*wp0.x + a42.y*wp1.x + a42.z*wp2.x + a42.w*wp3.x + a12*wp4.x;
            float zy = x2.y + xr.y + a42.x*wp0.y + a42.y*wp1.y + a42.z*wp2.y + a42.w*wp3.y + a12*wp4.y;
            float zz = x2.z + xr.z + a42.x*wp0.z + a42.y*wp1.z + a42.z*wp2.z + a42.w*wp3.z + a12*wp4.z;
            float zw = x2.w + xr.w + a42.x*wp0.w + a42.y*wp1.w + a42.z*wp2.w + a42.w*wp3.w + a12*wp4.w;
            zx = zx >= 0.f ? zx : 0.2f * zx; zy = zy >= 0.f ? zy : 0.2f * zy;
            zz = zz >= 0.f ? zz : 0.2f * zz; zw = zw >= 0.f ? zw : 0.2f * zw;
            p2 = zx*att.x + zy*att.y + zz*att.z + zw*att.w;
        }
        {
            float zx = x3.x + xr.x + a43.x*wp0.x + a43.y*wp1.x + a43.z*wp2.x + a43.w*wp3.x + a13*wp4.x;
            float zy = x3.y + xr.y + a43.x*wp0.y + a43.y*wp1.y + a43.z*wp2.y + a43.w*wp3.y + a13*wp4.y;
            float zz = x3.z + xr.z + a43.x*wp0.z + a43.y*wp1.z + a43.z*wp2.z + a43.w*wp3.z + a13*wp4.z;
            float zw = x3.w + xr.w + a43.x*wp0.w + a43.y*wp1.w + a43.z*wp2.w + a43.w*wp3.w + a13*wp4.w;
            zx = zx >= 0.f ? zx : 0.2f * zx; zy = zy >= 0.f ? zy : 0.2f * zy;
            zz = zz >= 0.f ? zz : 0.2f * zz; zw = zw >= 0.f ? zw : 0.2f * zw;
            p3 = zx*att.x + zy*att.y + zz*att.z + zw*att.w;
        }
        #pragma unroll
        for (int o = 8; o; o >>= 1) {   // reduce within 16-lane half-warp (one head)
            p0 += __shfl_xor_sync(FULLMASK, p0, o);
            p1 += __shfl_xor_sync(FULLMASK, p1, o);
            p2 += __shfl_xor_sync(FULLMASK, p2, o);
            p3 += __shfl_xor_sync(FULLMASK, p3, o);
        }
        float mx = fmaxf(fmaxf(fmaxf(p0, p1), fmaxf(p2, p3)), m);
        float f  = __expf(m - mx);
        float w0 = __expf(p0 - mx), w1 = __expf(p1 - mx),
              w2 = __expf(p2 - mx), w3 = __expf(p3 - mx);
        ssum = ssum * f + ((w0 + w1) + (w2 + w3));
        acc.x = acc.x * f + ((w0*x0.x + w1*x1.x) + (w2*x2.x + w3*x3.x));
        acc.y = acc.y * f + ((w0*x0.y + w1*x1.y) + (w2*x2.y + w3*x3.y));
        acc.z = acc.z * f + ((w0*x0.z + w1*x1.z) + (w2*x2.z + w3*x3.z));
        acc.w = acc.w * f + ((w0*x0.w + w1*x1.w) + (w2*x2.w + w3*x3.w));
        m = mx;
    }
    for (; i < d; i++) {
        int e = lst[i], s0 = sl[i];
        float4 x0 = *(const float4*)(g_xl + (long)s0 * 256 + c0);
        float4 a4 = g_ea4[e]; float a1e = g_ea1[e];
        float zx = x0.x + xr.x + a4.x*wp0.x + a4.y*wp1.x + a4.z*wp2.x + a4.w*wp3.x + a1e*wp4.x;
        float zy = x0.y + xr.y + a4.x*wp0.y + a4.y*wp1.y + a4.z*wp2.y + a4.w*wp3.y + a1e*wp4.y;
        float zz = x0.z + xr.z + a4.x*wp0.z + a4.y*wp1.z + a4.z*wp2.z + a4.w*wp3.z + a1e*wp4.z;
        float zw = x0.w + xr.w + a4.x*wp0.w + a4.y*wp1.w + a4.z*wp2.w + a4.w*wp3.w + a1e*wp4.w;
        zx = zx >= 0.f ? zx : 0.2f * zx; zy = zy >= 0.f ? zy : 0.2f * zy;
        zz = zz >= 0.f ? zz : 0.2f * zz; zw = zw >= 0.f ? zw : 0.2f * zw;
        float p0 = zx*att.x + zy*att.y + zz*att.z + zw*att.w;
        #pragma unroll
        for (int o = 8; o; o >>= 1) p0 += __shfl_xor_sync(FULLMASK, p0, o);
        float mx = fmaxf(m, p0);
        float f = __expf(m - mx), w0 = __expf(p0 - mx);
        ssum = ssum * f + w0;
        acc.x = acc.x * f + w0 * x0.x;
        acc.y = acc.y * f + w0 * x0.y;
        acc.z = acc.z * f + w0 * x0.z;
        acc.w = acc.w * f + w0 * x0.w;
        m = mx;
    }
    float inv = 1.f / (ssum + 1e-16f);
    float4 o4 = make_float4(acc.x * inv, acc.y * inv, acc.z * inv, acc.w * inv);
    *(float4*)(g_out + (long)n * 256 + c0) = o4;
    atomicAdd(&bsum[c0],     o4.x); atomicAdd(&bsq[c0],     o4.x * o4.x);
    atomicAdd(&bsum[c0 + 1], o4.y); atomicAdd(&bsq[c0 + 1], o4.y * o4.y);
    atomicAdd(&bsum[c0 + 2], o4.z); atomicAdd(&bsq[c0 + 2], o4.z * o4.z);
    atomicAdd(&bsum[c0 + 3], o4.w); atomicAdd(&bsq[c0 + 3], o4.w * o4.w);
    __syncthreads();
    if (t < HC) {
        atomicAdd(&csum[t], (double)bsum[t]);
        atomicAdd(&csq[t],  (double)bsq[t]);
    }
}

// ---------------- pool + classifier (BN+leaky of layer 1 fused in) -------------
__global__ void pool_k(const float* __restrict__ W, const float* __restrict__ bb,
                       const float* __restrict__ gam, const float* __restrict__ bet,
                       float* __restrict__ outp) {
    int g = blockIdx.x;
    int t = threadIdx.x;  // 256 = channel
    double mu_d  = g_csum1[t] * (1.0 / NN);
    double var_d = g_csq1[t] * (1.0 / NN) - mu_d * mu_d;
    float mu = (float)mu_d;
    float rs = rsqrtf((float)var_d + 1e-5f) * gam[t];
    float bt = bet[t];
    float s = 0.f;
    int base = g * N_ROI;
    for (int r = 0; r < N_ROI; r++) {
        float v = g_out[(base + r) * 256 + t];
        v = (v - mu) * rs + bt;
        v = v >= 0.f ? v : 0.01f * v;
        s += v;
    }
    s *= (1.f / (float)N_ROI);
    float c0 = s * W[t * 2], c1 = s * W[t * 2 + 1];
    __shared__ float r0s[8], r1s[8];
    for (int o = 16; o; o >>= 1) {
        c0 += __shfl_down_sync(FULLMASK, c0, o);
        c1 += __shfl_down_sync(FULLMASK, c1, o);
    }
    if ((t & 31) == 0) { r0s[t >> 5] = c0; r1s[t >> 5] = c1; }
    __syncthreads();
    if (t == 0) {
        float a = 0.f, b2 = 0.f;
        for (int i = 0; i < 8; i++) { a += r0s[i]; b2 += r1s[i]; }
        outp[g * 2]     = a  + bb[0];
        outp[g * 2 + 1] = b2 + bb[1];
    }
}

// ---------------- launch --------------------------------------------------------
extern "C" void kernel_launch(void* const* d_in, const int* in_sizes, int n_in,
                              void* d_out, int out_size) {
    const float* x          = (const float*)d_in[0];
    const int*   edge_index = (const int*)  d_in[1];
    const float* edge_attr  = (const float*)d_in[2];
    const int*   node_group = (const int*)  d_in[4];
    const float* group_emb  = (const float*)d_in[5];
    const float* W_embed    = (const float*)d_in[6];
    const float* b_embed    = (const float*)d_in[7];
    const float* We_enc     = (const float*)d_in[8];
    const float* be_enc     = (const float*)d_in[9];
    const float* W1         = (const float*)d_in[10];
    const float* b1         = (const float*)d_in[11];
    const float* W2         = (const float*)d_in[12];
    const float* b2         = (const float*)d_in[13];
    const float* ln_g       = (const float*)d_in[14];
    const float* ln_b       = (const float*)d_in[15];
    const float* l0_Wl      = (const float*)d_in[16];
    const float* l0_Wr      = (const float*)d_in[17];
    const float* l0_We      = (const float*)d_in[18];
    const float* l0_att     = (const float*)d_in[19];
    const float* l0_bn_g    = (const float*)d_in[21];
    const float* l0_bn_b    = (const float*)d_in[22];
    const float* l1_Wl      = (const float*)d_in[23];
    const float* l1_Wr      = (const float*)d_in[24];
    const float* l1_We      = (const float*)d_in[25];
    const float* l1_att     = (const float*)d_in[26];
    const float* l1_bn_g    = (const float*)d_in[28];
    const float* l1_bn_b    = (const float*)d_in[29];
    const float* fc2_W      = (const float*)d_in[30];
    const float* fc2_b      = (const float*)d_in[31];

    const int* srcp = edge_index;
    const int* dstp = edge_index + EE;

    double* csum0; double* csq0; double* csum1; double* csq1;
    cudaGetSymbolAddress((void**)&csum0, g_csum0);
    cudaGetSymbolAddress((void**)&csq0,  g_csq0);
    cudaGetSymbolAddress((void**)&csum1, g_csum1);
    cudaGetSymbolAddress((void**)&csq1,  g_csq1);

    // 1: fused prologue (embed | adjacency | ea repack | stat zero)
    prologue_k<<<PB_TOTAL, 256>>>(x, node_group, group_emb, W_embed, b_embed,
                                  srcp, dstp, edge_attr);
    // 2
    gine_k<<<NN, 64>>>(We_enc, be_enc, W1, b1, W2, b2, ln_g, ln_b);
    // 3
    xlxr0_k<<<NN / 16, 256>>>(l0_Wl, l0_Wr);
    // 4 (profiled): GAT layer 0
    gat_warp_k<<<NN / 4, 256>>>(l0_We, l0_att, csum0, csq0);
    // 5: GAT layer 1 projection (BN of layer 0 fused)
    xlxr1_k<<<NN / 16, 256>>>(l1_Wl, l1_Wr, l0_bn_g, l0_bn_b);
    // 6: GAT layer 1
    gat_warp_k<<<NN / 4, 256>>>(l1_We, l1_att, csum1, csq1);
    // 7: pool + classifier (BN of layer 1 fused)
    pool_k<<<G, 256>>>(fc2_W, fc2_b, l1_bn_g, l1_bn_b, (float*)d_out);
}